// round 12
// baseline (speedup 1.0000x reference)
#include <cuda_runtime.h>
#include <cuda_fp16.h>
#include <math.h>
#include <stdint.h>

typedef uint32_t u32;

static constexpr int kT = 512;
static constexpr int kB = 64;
static constexpr int kH = 1024;
static constexpr int kG = 4096;
static constexpr int RBLK = 64;     // recurrence blocks (16 j-cols each)

// ---------------- global scratch ----------------
__device__ __half g_xg16[(size_t)kT * kB * kG];    // x-gates fp16 (biases included)
__device__ __half g_x16[(size_t)kT * kB * kH];     // x fp16
__device__ __half g_wih[(size_t)kG * kH];          // W_ih fp16
__device__ __half g_wp[(size_t)kG * kH];           // W_hh fp16 packed [jblk][row][k]
__device__ __half g_h16[2][kB * kH];               // h fp16, double buffered [b][k]
__device__ unsigned g_cnt, g_rel;

// ---------------- PTX helpers ----------------
__device__ __forceinline__ u32 smem_u32(const void* p) {
    u32 a;
    asm("{ .reg .u64 t; cvta.to.shared.u64 t, %1; cvt.u32.u64 %0, t; }" : "=r"(a) : "l"(p));
    return a;
}
__device__ __forceinline__ void cp16(u32 dst, const void* src) {
    asm volatile("cp.async.cg.shared.global [%0], [%1], 16;" :: "r"(dst), "l"(src) : "memory");
}
__device__ __forceinline__ void cp_commit() { asm volatile("cp.async.commit_group;" ::: "memory"); }
__device__ __forceinline__ void cp_wait0()  { asm volatile("cp.async.wait_group 0;" ::: "memory"); }
__device__ __forceinline__ void cp_wait1()  { asm volatile("cp.async.wait_group 1;" ::: "memory"); }

__device__ __forceinline__ void ldm4(u32 a, u32* r) {
    asm volatile("ldmatrix.sync.aligned.m8n8.x4.shared.b16 {%0,%1,%2,%3}, [%4];"
                 : "=r"(r[0]), "=r"(r[1]), "=r"(r[2]), "=r"(r[3]) : "r"(a));
}
__device__ __forceinline__ void mma_fp16(float* c, const u32* a, u32 b0, u32 b1) {
    asm volatile("mma.sync.aligned.m16n8k16.row.col.f32.f16.f16.f32 "
                 "{%0,%1,%2,%3}, {%4,%5,%6,%7}, {%8,%9}, {%0,%1,%2,%3};"
                 : "+f"(c[0]), "+f"(c[1]), "+f"(c[2]), "+f"(c[3])
                 : "r"(a[0]), "r"(a[1]), "r"(a[2]), "r"(a[3]), "r"(b0), "r"(b1));
}
// swizzled byte offset: row r, 16B-unit u, row stride bytes (multiple of 128)
__device__ __forceinline__ u32 swof(int r, int u, int stride) {
    return (u32)(r * stride + ((u >> 3) << 7) + (((u ^ r) & 7) << 4));
}

__device__ __forceinline__ float sigf(float x) { return 1.f / (1.f + __expf(-x)); }
__device__ __forceinline__ float tanh_fast(float x) {
    float t = 2.f / (__expf(2.f * fabsf(x)) + 1.f);
    float r = 1.f - t;
    return x >= 0.f ? r : -r;
}

// ---------------- prep kernels ----------------
__global__ void init_sync() { g_cnt = 0u; g_rel = 0u; }

__global__ void split_x16(const float* __restrict__ s, int n) {
    for (int i = blockIdx.x * blockDim.x + threadIdx.x; i < n; i += gridDim.x * blockDim.x)
        g_x16[i] = __float2half_rn(s[i]);
}
__global__ void split_wih(const float* __restrict__ s, int n) {
    for (int i = blockIdx.x * blockDim.x + threadIdx.x; i < n; i += gridDim.x * blockDim.x)
        g_wih[i] = __float2half_rn(s[i]);
}
__global__ void split_h0_16(const float* __restrict__ s, int n) {
    for (int i = blockIdx.x * blockDim.x + threadIdx.x; i < n; i += gridDim.x * blockDim.x)
        g_h16[0][i] = __float2half_rn(s[i]);
}
// g_wp[(jblk*64 + row)*1024 + k], row = g*16 + jl, src row = g*1024 + jblk*16 + jl
__global__ void pack_whh16(const float* __restrict__ whh) {
    const int n = kG * kH;
    for (int i = blockIdx.x * blockDim.x + threadIdx.x; i < n; i += gridDim.x * blockDim.x) {
        int k    = i & 1023;
        int row  = (i >> 10) & 63;
        int jblk = i >> 16;
        int g = row >> 4, jl = row & 15;
        g_wp[i] = __float2half_rn(whh[(size_t)(g * kH + jblk * 16 + jl) * kH + k]);
    }
}

// ============================================================================
// Phase 1: x-gates GEMM (fp16 HMMA). C = x @ Wih^T + biases -> fp16 out.
// 128x128 tile, 256 thr, warp tile 32x64. K chunks of 64, double buffered.
// ============================================================================
static constexpr int XA   = 0;
static constexpr int XWH  = 16384;
static constexpr int XBUFSZ = 32768;
static constexpr int XBIAS  = 2 * XBUFSZ;
static constexpr int XG_SMEM = XBIAS + 512;

__global__ __launch_bounds__(256, 2) void xgates_tc(
    const float* __restrict__ bih, const float* __restrict__ bhh)
{
    extern __shared__ char sm[];
    const u32 sb  = smem_u32(sm);
    const int tid = threadIdx.x;
    const int wid = tid >> 5;
    const int ln  = tid & 31;
    const int mg  = wid & 3;
    const int ng  = wid >> 2;
    const int n0  = blockIdx.x * 128;
    const int m0  = blockIdx.y * 128;
    float* bias_s = (float*)(sm + XBIAS);

    if (tid < 128) bias_s[tid] = bih[n0 + tid] + bhh[n0 + tid];

    auto stage = [&](int ch, u32 buf) {
        #pragma unroll
        for (int rep = 0; rep < 4; rep++) {
            int idx = tid + rep * 256;
            int r = idx >> 3, u = idx & 7;
            u32 sw = swof(r, u, 128);
            cp16(buf + XA  + sw, (const char*)g_x16 + ((size_t)(m0 + r) * kH + ch * 64 + u * 8) * 2);
            cp16(buf + XWH + sw, (const char*)g_wih + ((size_t)(n0 + r) * kH + ch * 64 + u * 8) * 2);
        }
        cp_commit();
    };

    float c[2][8][4];
    #pragma unroll
    for (int i = 0; i < 2; i++)
        #pragma unroll
        for (int j = 0; j < 8; j++)
            #pragma unroll
            for (int q = 0; q < 4; q++) c[i][j][q] = 0.f;

    stage(0, sb);
    for (int ch = 0; ch < 16; ch++) {
        const u32 buf = sb + (ch & 1) * XBUFSZ;
        if (ch < 15) { stage(ch + 1, sb + ((ch + 1) & 1) * XBUFSZ); cp_wait1(); }
        else cp_wait0();
        __syncthreads();
        #pragma unroll
        for (int k2 = 0; k2 < 4; k2++) {
            u32 ah[2][4];
            #pragma unroll
            for (int mt = 0; mt < 2; mt++) {
                int r = mg * 32 + mt * 16 + (ln & 15);
                int u = k2 * 2 + (ln >> 4);
                ldm4(buf + XA + swof(r, u, 128), ah[mt]);
            }
            u32 bh[4][4];
            #pragma unroll
            for (int p = 0; p < 4; p++) {
                int r = ng * 64 + p * 16 + (ln & 7) + ((ln & 16) >> 1);
                int u = k2 * 2 + ((ln >> 3) & 1);
                ldm4(buf + XWH + swof(r, u, 128), bh[p]);
            }
            #pragma unroll
            for (int mt = 0; mt < 2; mt++)
                #pragma unroll
                for (int nt = 0; nt < 8; nt++) {
                    const int p = nt >> 1, o = (nt & 1) * 2;
                    mma_fp16(c[mt][nt], ah[mt], bh[p][o], bh[p][o + 1]);
                }
        }
        __syncthreads();
    }

    // epilogue: add bias, store fp16 pairs
    #pragma unroll
    for (int mt = 0; mt < 2; mt++) {
        const int row = m0 + mg * 32 + mt * 16 + (ln >> 2);
        #pragma unroll
        for (int nt = 0; nt < 8; nt++) {
            const int col = ng * 64 + nt * 8 + (ln & 3) * 2;
            float b0 = bias_s[col], b1 = bias_s[col + 1];
            __half2 v0 = __floats2half2_rn(c[mt][nt][0] + b0, c[mt][nt][1] + b1);
            __half2 v1 = __floats2half2_rn(c[mt][nt][2] + b0, c[mt][nt][3] + b1);
            *(__half2*)(g_xg16 + (size_t)row * kG + n0 + col)       = v0;
            *(__half2*)(g_xg16 + (size_t)(row + 8) * kG + n0 + col) = v1;
        }
    }
}

// ============================================================================
// Phase 2: persistent recurrence. 64 blocks x 512 threads.
// Block jblk: C[64 gate-rows, 64 batch] = Wslice @ h^T. W fp16 resident (128 KB).
// h fp16 streamed: 4 chunks of K=256 (32 KB), 2 buffers.
// 16 warps: mg(4) x ng(4), warp tile 16x16 over full K -> NO ks reduction.
// c-state in regs. Single-counter barrier (R7-style).
// ============================================================================
static constexpr int RWH   = 0;                  // 128 KB resident W
static constexpr int RBUF  = 131072;             // 2 x 32 KB h chunk buffers
static constexpr int RACT  = RBUF + 65536;       // 196608 : 64*68 fp32 = 17408
static constexpr int RC_SMEM = RACT + 17408;     // 214016

__global__ __launch_bounds__(512, 1) void lstm_tc(
    const float* __restrict__ c0, float* __restrict__ out)
{
    extern __shared__ char sm[];
    const u32 sb  = smem_u32(sm);
    const int tid = threadIdx.x;
    const int wid = tid >> 5;
    const int ln  = tid & 31;
    const int jblk = blockIdx.x;
    const int j0   = jblk * 16;
    const int mg = wid & 3, ng = wid >> 2;   // warp tile: rows mg*16.., cols ng*16..
    float* act = (float*)(sm + RACT);

    // resident W load: 64 rows x 128 units, swizzled, stride 2048 B
    #pragma unroll
    for (int rep = 0; rep < 16; rep++) {
        int idx = tid + rep * 512;       // 0..8191
        int r = idx >> 7, u = idx & 127;
        cp16(sb + RWH + swof(r, u, 2048),
             (const char*)g_wp + ((size_t)(jblk * 64 + r) * kH + u * 8) * 2);
    }
    cp_commit();

    // cell ownership: b = tid>>3 (0..63), jl pair = (tid&7)*2 ; c-state in regs
    const int cb   = tid >> 3;
    const int cjl2 = (tid & 7) << 2 >> 1;   // (tid&7)*2
    float creg0 = c0[(size_t)cb * kH + j0 + cjl2];
    float creg1 = c0[(size_t)cb * kH + j0 + cjl2 + 1];

    cp_wait0();
    __syncthreads();

    for (int t = 0; t < kT; t++) {
        const __half* hsrc = g_h16[t & 1];

        // x-gates prefetch: 4 gates x half2 (pair of adjacent j)
        __half2 xg2[4];
        {
            const __half* xp = g_xg16 + ((size_t)t * kB + cb) * kG + j0 + cjl2;
            #pragma unroll
            for (int g = 0; g < 4; g++) xg2[g] = *(const __half2*)(xp + g * kH);
        }

        // stage chunk ch (64 rows x 32 units, K=256) into buffer
        auto stage = [&](int ch, u32 buf) {
            #pragma unroll
            for (int rep = 0; rep < 4; rep++) {
                int idx = tid + rep * 512;   // 0..2047
                int r = idx >> 5, u = idx & 31;
                cp16(buf + swof(r, u, 512),
                     (const char*)hsrc + ((size_t)r * kH + ch * 256 + u * 8) * 2);
            }
            cp_commit();
        };

        float cc[2][4];
        #pragma unroll
        for (int i = 0; i < 2; i++)
            #pragma unroll
            for (int q = 0; q < 4; q++) cc[i][q] = 0.f;

        // MMA over one staged chunk ci at buffer buf
        auto mma_chunk = [&](int ci, u32 buf) {
            #pragma unroll
            for (int k2 = 0; k2 < 16; k2++) {
                const int gk = ci * 16 + k2;     // global k16 index 0..63
                u32 aa[4], bb[4];
                {
                    int r = mg * 16 + (ln & 15);
                    int u = gk * 2 + (ln >> 4);
                    ldm4(sb + RWH + swof(r, u, 2048), aa);
                }
                {
                    int r = ng * 16 + (ln & 7) + ((ln & 16) >> 1);
                    int u = k2 * 2 + ((ln >> 3) & 1);
                    ldm4(buf + swof(r, u, 512), bb);
                }
                mma_fp16(cc[0], aa, bb[0], bb[1]);
                mma_fp16(cc[1], aa, bb[2], bb[3]);
            }
        };

        const u32 b0 = sb + RBUF, b1 = sb + RBUF + 32768;
        stage(0, b0);
        stage(1, b1);
        cp_wait1(); __syncthreads();
        mma_chunk(0, b0);
        __syncthreads();
        stage(2, b0);
        cp_wait1(); __syncthreads();
        mma_chunk(1, b1);
        __syncthreads();
        stage(3, b1);
        cp_wait1(); __syncthreads();
        mma_chunk(2, b0);
        cp_wait0(); __syncthreads();
        mma_chunk(3, b1);

        // C frags -> act[row][col] (single pass, no K reduction)
        {
            const int r0  = mg * 16 + (ln >> 2);
            const int col = ng * 16 + (ln & 3) * 2;
            *(float2*)(act + r0 * 68 + col)           = make_float2(cc[0][0], cc[0][1]);
            *(float2*)(act + (r0 + 8) * 68 + col)     = make_float2(cc[0][2], cc[0][3]);
            *(float2*)(act + r0 * 68 + col + 8)       = make_float2(cc[1][0], cc[1][1]);
            *(float2*)(act + (r0 + 8) * 68 + col + 8) = make_float2(cc[1][2], cc[1][3]);
        }
        __syncthreads();

        // fused cell update: 2 cells per thread (cb, cjl2) and (cb, cjl2+1)
        {
            float2 hv;
            #pragma unroll
            for (int q = 0; q < 2; q++) {
                const int jl = cjl2 + q;
                float xf[4];
                #pragma unroll
                for (int g = 0; g < 4; g++) {
                    float2 p = __half22float2(xg2[g]);
                    xf[g] = q ? p.y : p.x;
                }
                float gi = sigf(act[(0 * 16 + jl) * 68 + cb] + xf[0]);
                float gf = sigf(act[(1 * 16 + jl) * 68 + cb] + xf[1]);
                float gg = tanh_fast(act[(2 * 16 + jl) * 68 + cb] + xf[2]);
                float go = sigf(act[(3 * 16 + jl) * 68 + cb] + xf[3]);
                float& cr = q ? creg1 : creg0;
                cr = gf * cr + gi * gg;
                float hy = go * tanh_fast(cr);
                (q ? hv.y : hv.x) = hy;
            }
            *(float2*)(out + ((size_t)t * kB + cb) * kH + j0 + cjl2) = hv;
            *(__half2*)(g_h16[(t & 1) ^ 1] + (size_t)cb * kH + j0 + cjl2) =
                __floats2half2_rn(hv.x, hv.y);
        }

        // single-counter grid barrier between steps (R7-style, 64 arrivals)
        if (t < kT - 1) {
            __threadfence();
            __syncthreads();
            if (tid == 0) {
                unsigned a = atomicAdd(&g_cnt, 1u) + 1u;
                if (a == (unsigned)(t + 1) * RBLK) {
                    __threadfence();
                    atomicExch(&g_rel, (unsigned)(t + 1));
                } else {
                    while (*((volatile unsigned*)&g_rel) < (unsigned)(t + 1)) { }
                }
            }
            __syncthreads();
        }
    }

    // final cell state
    *(float2*)(out + (size_t)kT * kB * kH + (size_t)cb * kH + j0 + cjl2) =
        make_float2(creg0, creg1);
}

// ============================================================================
extern "C" void kernel_launch(void* const* d_in, const int* in_sizes, int n_in,
                              void* d_out, int out_size) {
    const float* x   = (const float*)d_in[0];
    const float* h0  = (const float*)d_in[1];
    const float* c0  = (const float*)d_in[2];
    const float* wih = (const float*)d_in[3];
    const float* whh = (const float*)d_in[4];
    const float* bih = (const float*)d_in[5];
    const float* bhh = (const float*)d_in[6];
    float* out = (float*)d_out;

    static bool attr_set = false;
    if (!attr_set) {
        cudaFuncSetAttribute(xgates_tc, cudaFuncAttributeMaxDynamicSharedMemorySize, XG_SMEM);
        cudaFuncSetAttribute(lstm_tc,   cudaFuncAttributeMaxDynamicSharedMemorySize, RC_SMEM);
        attr_set = true;
    }

    init_sync<<<1, 1>>>();
    split_x16<<<4096, 256>>>(x, kT * kB * kH);
    split_wih<<<1024, 256>>>(wih, kG * kH);
    split_h0_16<<<64, 256>>>(h0, kB * kH);
    pack_whh16<<<1024, 256>>>(whh);
    xgates_tc<<<dim3(kG / 128, (kT * kB) / 128), 256, XG_SMEM>>>(bih, bhh);
    lstm_tc<<<RBLK, 512, RC_SMEM>>>(c0, out);
}

// round 13
// speedup vs baseline: 1.3567x; 1.3567x over previous
#include <cuda_runtime.h>
#include <cuda_fp16.h>
#include <math.h>
#include <stdint.h>

typedef uint32_t u32;

static constexpr int kT = 512;
static constexpr int kB = 64;
static constexpr int kH = 1024;
static constexpr int kG = 4096;
static constexpr int RBLK = 128;

// ---------------- global scratch ----------------
__device__ __half g_xg16[(size_t)kT * kB * kG];    // x-gates fp16 (biases included)
__device__ __half g_x16[(size_t)kT * kB * kH];     // x fp16
__device__ __half g_wih[(size_t)kG * kH];          // W_ih fp16
__device__ __half g_wp[(size_t)kG * kH];           // W_hh fp16 packed [jblk][row][k]
__device__ __half g_h16[2][kB * kH];               // h fp16, double buffered [b][k]
__device__ unsigned g_cnt, g_rel;

// ---------------- PTX helpers ----------------
__device__ __forceinline__ u32 smem_u32(const void* p) {
    u32 a;
    asm("{ .reg .u64 t; cvta.to.shared.u64 t, %1; cvt.u32.u64 %0, t; }" : "=r"(a) : "l"(p));
    return a;
}
__device__ __forceinline__ void cp16(u32 dst, const void* src) {
    asm volatile("cp.async.cg.shared.global [%0], [%1], 16;" :: "r"(dst), "l"(src) : "memory");
}
__device__ __forceinline__ void cp_commit() { asm volatile("cp.async.commit_group;" ::: "memory"); }
__device__ __forceinline__ void cp_wait0()  { asm volatile("cp.async.wait_group 0;" ::: "memory"); }
__device__ __forceinline__ void cp_wait1()  { asm volatile("cp.async.wait_group 1;" ::: "memory"); }

__device__ __forceinline__ void ldm4(u32 a, u32* r) {
    asm volatile("ldmatrix.sync.aligned.m8n8.x4.shared.b16 {%0,%1,%2,%3}, [%4];"
                 : "=r"(r[0]), "=r"(r[1]), "=r"(r[2]), "=r"(r[3]) : "r"(a));
}
__device__ __forceinline__ void mma_fp16(float* c, const u32* a, u32 b0, u32 b1) {
    asm volatile("mma.sync.aligned.m16n8k16.row.col.f32.f16.f16.f32 "
                 "{%0,%1,%2,%3}, {%4,%5,%6,%7}, {%8,%9}, {%0,%1,%2,%3};"
                 : "+f"(c[0]), "+f"(c[1]), "+f"(c[2]), "+f"(c[3])
                 : "r"(a[0]), "r"(a[1]), "r"(a[2]), "r"(a[3]), "r"(b0), "r"(b1));
}
// swizzled byte offset: row r, 16B-unit u, row stride bytes (multiple of 128)
__device__ __forceinline__ u32 swof(int r, int u, int stride) {
    return (u32)(r * stride + ((u >> 3) << 7) + (((u ^ r) & 7) << 4));
}

__device__ __forceinline__ float sigf(float x) { return 1.f / (1.f + __expf(-x)); }
__device__ __forceinline__ float tanh_fast(float x) {
    float t = 2.f / (__expf(2.f * fabsf(x)) + 1.f);
    float r = 1.f - t;
    return x >= 0.f ? r : -r;
}

// ---------------- prep kernels ----------------
__global__ void init_sync() { g_cnt = 0u; g_rel = 0u; }

__global__ void split_x16(const float* __restrict__ s, int n) {
    for (int i = blockIdx.x * blockDim.x + threadIdx.x; i < n; i += gridDim.x * blockDim.x)
        g_x16[i] = __float2half_rn(s[i]);
}
__global__ void split_wih(const float* __restrict__ s, int n) {
    for (int i = blockIdx.x * blockDim.x + threadIdx.x; i < n; i += gridDim.x * blockDim.x)
        g_wih[i] = __float2half_rn(s[i]);
}
__global__ void split_h0_16(const float* __restrict__ s, int n) {
    for (int i = blockIdx.x * blockDim.x + threadIdx.x; i < n; i += gridDim.x * blockDim.x)
        g_h16[0][i] = __float2half_rn(s[i]);
}
// g_wp[(jblk*32 + row)*1024 + k], row = g*8 + jl, src row = g*1024 + jblk*8 + jl
__global__ void pack_whh16(const float* __restrict__ whh) {
    const int n = kG * kH;
    for (int i = blockIdx.x * blockDim.x + threadIdx.x; i < n; i += gridDim.x * blockDim.x) {
        int k    = i & 1023;
        int row  = (i >> 10) & 31;
        int jblk = i >> 15;
        int g = row >> 3, jl = row & 7;
        g_wp[i] = __float2half_rn(whh[(size_t)(g * kH + jblk * 8 + jl) * kH + k]);
    }
}

// ============================================================================
// Phase 1: x-gates GEMM (fp16 HMMA). C = x @ Wih^T + biases -> fp16 out.
// 128x128 tile, 256 thr, warp tile 32x64. K chunks of 64, double buffered.
// ============================================================================
static constexpr int XA   = 0;
static constexpr int XWH  = 16384;
static constexpr int XBUFSZ = 32768;
static constexpr int XBIAS  = 2 * XBUFSZ;
static constexpr int XG_SMEM = XBIAS + 512;

__global__ __launch_bounds__(256, 2) void xgates_tc(
    const float* __restrict__ bih, const float* __restrict__ bhh)
{
    extern __shared__ char sm[];
    const u32 sb  = smem_u32(sm);
    const int tid = threadIdx.x;
    const int wid = tid >> 5;
    const int ln  = tid & 31;
    const int mg  = wid & 3;
    const int ng  = wid >> 2;
    const int n0  = blockIdx.x * 128;
    const int m0  = blockIdx.y * 128;
    float* bias_s = (float*)(sm + XBIAS);

    if (tid < 128) bias_s[tid] = bih[n0 + tid] + bhh[n0 + tid];

    auto stage = [&](int ch, u32 buf) {
        #pragma unroll
        for (int rep = 0; rep < 4; rep++) {
            int idx = tid + rep * 256;
            int r = idx >> 3, u = idx & 7;
            u32 sw = swof(r, u, 128);
            cp16(buf + XA  + sw, (const char*)g_x16 + ((size_t)(m0 + r) * kH + ch * 64 + u * 8) * 2);
            cp16(buf + XWH + sw, (const char*)g_wih + ((size_t)(n0 + r) * kH + ch * 64 + u * 8) * 2);
        }
        cp_commit();
    };

    float c[2][8][4];
    #pragma unroll
    for (int i = 0; i < 2; i++)
        #pragma unroll
        for (int j = 0; j < 8; j++)
            #pragma unroll
            for (int q = 0; q < 4; q++) c[i][j][q] = 0.f;

    stage(0, sb);
    for (int ch = 0; ch < 16; ch++) {
        const u32 buf = sb + (ch & 1) * XBUFSZ;
        if (ch < 15) { stage(ch + 1, sb + ((ch + 1) & 1) * XBUFSZ); cp_wait1(); }
        else cp_wait0();
        __syncthreads();
        #pragma unroll
        for (int k2 = 0; k2 < 4; k2++) {
            u32 ah[2][4];
            #pragma unroll
            for (int mt = 0; mt < 2; mt++) {
                int r = mg * 32 + mt * 16 + (ln & 15);
                int u = k2 * 2 + (ln >> 4);
                ldm4(buf + XA + swof(r, u, 128), ah[mt]);
            }
            u32 bh[4][4];
            #pragma unroll
            for (int p = 0; p < 4; p++) {
                int r = ng * 64 + p * 16 + (ln & 7) + ((ln & 16) >> 1);
                int u = k2 * 2 + ((ln >> 3) & 1);
                ldm4(buf + XWH + swof(r, u, 128), bh[p]);
            }
            #pragma unroll
            for (int mt = 0; mt < 2; mt++)
                #pragma unroll
                for (int nt = 0; nt < 8; nt++) {
                    const int p = nt >> 1, o = (nt & 1) * 2;
                    mma_fp16(c[mt][nt], ah[mt], bh[p][o], bh[p][o + 1]);
                }
        }
        __syncthreads();
    }

    // epilogue: add bias, store fp16 pairs
    #pragma unroll
    for (int mt = 0; mt < 2; mt++) {
        const int row = m0 + mg * 32 + mt * 16 + (ln >> 2);
        #pragma unroll
        for (int nt = 0; nt < 8; nt++) {
            const int col = ng * 64 + nt * 8 + (ln & 3) * 2;
            float b0 = bias_s[col], b1 = bias_s[col + 1];
            __half2 v0 = __floats2half2_rn(c[mt][nt][0] + b0, c[mt][nt][1] + b1);
            __half2 v1 = __floats2half2_rn(c[mt][nt][2] + b0, c[mt][nt][3] + b1);
            *(__half2*)(g_xg16 + (size_t)row * kG + n0 + col)       = v0;
            *(__half2*)(g_xg16 + (size_t)(row + 8) * kG + n0 + col) = v1;
        }
    }
}

// ============================================================================
// Phase 2: persistent recurrence (R7 structure, 4-chunk pipeline).
// 128 blocks x 512 threads. Block jblk: C[32 gate-rows, 64 batch] = Wslice @ h^T.
// W fp16 resident (64 KB). h: 4 chunks of K=256 (32 KB), 2 buffers, pipelined.
// 16 warps: mg(2) x ng(4) x ks(2). Warp tile 16x16, 2 accumulators. c in regs.
// Single-counter barrier (R7-style).
// ============================================================================
static constexpr int RWH   = 0;                 // 64 KB resident W
static constexpr int RBUF  = 65536;             // 2 x 32 KB h chunk buffers
static constexpr int RRED  = RBUF + 65536;      // 131072 : 2*32*68 fp32 = 17408
static constexpr int RC_SMEM = RRED + 17408;    // 148480

__global__ __launch_bounds__(512, 1) void lstm_tc(
    const float* __restrict__ c0, float* __restrict__ out)
{
    extern __shared__ char sm[];
    const u32 sb  = smem_u32(sm);
    const int tid = threadIdx.x;
    const int wid = tid >> 5;
    const int ln  = tid & 31;
    const int jblk = blockIdx.x;
    const int j0   = jblk * 8;
    const int mg = wid & 1, ng = (wid >> 1) & 3, ks = wid >> 3;
    float* red = (float*)(sm + RRED);

    // resident W load: 32 rows x 128 units, swizzled, stride 2048 B
    #pragma unroll
    for (int rep = 0; rep < 8; rep++) {
        int idx = tid + rep * 512;
        int r = idx >> 7, u = idx & 127;
        cp16(sb + RWH + swof(r, u, 2048),
             (const char*)g_wp + ((size_t)(jblk * 32 + r) * kH + u * 8) * 2);
    }
    cp_commit();

    // cell ownership: b = tid>>3, jl = tid&7 ; c-state in a register
    const int cb  = tid >> 3;
    const int cjl = tid & 7;
    float creg = c0[(size_t)cb * kH + j0 + cjl];

    cp_wait0();
    __syncthreads();

    for (int t = 0; t < kT; t++) {
        const __half* hsrc = g_h16[t & 1];

        // x-gates prefetch (fp16, biases included)
        float xgv[4];
        {
            const __half* xp = g_xg16 + ((size_t)t * kB + cb) * kG + j0 + cjl;
            #pragma unroll
            for (int g = 0; g < 4; g++) xgv[g] = __half2float(xp[g * kH]);
        }

        // stage chunk ch (64 rows x 32 units, K=256) into buffer
        auto stage = [&](int ch, u32 buf) {
            #pragma unroll
            for (int rep = 0; rep < 4; rep++) {
                int idx = tid + rep * 512;   // 0..2047
                int r = idx >> 5, u = idx & 31;
                cp16(buf + swof(r, u, 512),
                     (const char*)hsrc + ((size_t)r * kH + ch * 256 + u * 8) * 2);
            }
            cp_commit();
        };

        float cc[2][4];
        #pragma unroll
        for (int i = 0; i < 2; i++)
            #pragma unroll
            for (int q = 0; q < 4; q++) cc[i][q] = 0.f;

        // MMA over one staged chunk ci (K=256 -> 16 k16, split over ks(2))
        auto mma_chunk = [&](int ci, u32 buf) {
            #pragma unroll
            for (int k2 = 0; k2 < 8; k2++) {
                const int lk = ks * 8 + k2;          // local k16 in chunk 0..15
                const int gk = ci * 16 + lk;         // global k16 0..63
                u32 aa[4], bb[4];
                {
                    int r = mg * 16 + (ln & 15);
                    int u = gk * 2 + (ln >> 4);
                    ldm4(sb + RWH + swof(r, u, 2048), aa);
                }
                {
                    int r = ng * 16 + (ln & 7) + ((ln & 16) >> 1);
                    int u = lk * 2 + ((ln >> 3) & 1);
                    ldm4(buf + swof(r, u, 512), bb);
                }
                mma_fp16(cc[0], aa, bb[0], bb[1]);
                mma_fp16(cc[1], aa, bb[2], bb[3]);
            }
        };

        const u32 b0 = sb + RBUF, b1 = sb + RBUF + 32768;
        stage(0, b0);
        stage(1, b1);
        cp_wait1(); __syncthreads();
        mma_chunk(0, b0);
        __syncthreads();                 // all reads of b0 done
        stage(2, b0);
        cp_wait1(); __syncthreads();     // chunk1 resident
        mma_chunk(1, b1);
        __syncthreads();                 // all reads of b1 done
        stage(3, b1);
        cp_wait1(); __syncthreads();     // chunk2 resident
        mma_chunk(2, b0);
        cp_wait0(); __syncthreads();     // chunk3 resident
        mma_chunk(3, b1);

        // C frags -> red[ks][row][col]
        {
            float* rp = red + ks * (32 * 68);
            const int r0  = mg * 16 + (ln >> 2);
            const int col = ng * 16 + (ln & 3) * 2;
            *(float2*)(rp + r0 * 68 + col)           = make_float2(cc[0][0], cc[0][1]);
            *(float2*)(rp + (r0 + 8) * 68 + col)     = make_float2(cc[0][2], cc[0][3]);
            *(float2*)(rp + r0 * 68 + col + 8)       = make_float2(cc[1][0], cc[1][1]);
            *(float2*)(rp + (r0 + 8) * 68 + col + 8) = make_float2(cc[1][2], cc[1][3]);
        }
        __syncthreads();

        // fused cell update (c-state in register)
        {
            float gv[4];
            #pragma unroll
            for (int g = 0; g < 4; g++) {
                const int row = g * 8 + cjl;
                gv[g] = red[row * 68 + cb] + red[32 * 68 + row * 68 + cb] + xgv[g];
            }
            float gi = sigf(gv[0]);
            float gf = sigf(gv[1]);
            float gg = tanh_fast(gv[2]);
            float go = sigf(gv[3]);
            creg = gf * creg + gi * gg;
            float hy = go * tanh_fast(creg);
            out[((size_t)t * kB + cb) * kH + j0 + cjl] = hy;
            g_h16[(t & 1) ^ 1][(size_t)cb * kH + j0 + cjl] = __float2half_rn(hy);
        }

        // single-counter grid barrier between steps
        if (t < kT - 1) {
            __threadfence();
            __syncthreads();
            if (tid == 0) {
                unsigned a = atomicAdd(&g_cnt, 1u) + 1u;
                if (a == (unsigned)(t + 1) * RBLK) {
                    __threadfence();
                    atomicExch(&g_rel, (unsigned)(t + 1));
                } else {
                    while (*((volatile unsigned*)&g_rel) < (unsigned)(t + 1)) { }
                }
            }
            __syncthreads();
        }
    }

    // final cell state
    out[(size_t)kT * kB * kH + (size_t)cb * kH + j0 + cjl] = creg;
}

// ============================================================================
extern "C" void kernel_launch(void* const* d_in, const int* in_sizes, int n_in,
                              void* d_out, int out_size) {
    const float* x   = (const float*)d_in[0];
    const float* h0  = (const float*)d_in[1];
    const float* c0  = (const float*)d_in[2];
    const float* wih = (const float*)d_in[3];
    const float* whh = (const float*)d_in[4];
    const float* bih = (const float*)d_in[5];
    const float* bhh = (const float*)d_in[6];
    float* out = (float*)d_out;

    static bool attr_set = false;
    if (!attr_set) {
        cudaFuncSetAttribute(xgates_tc, cudaFuncAttributeMaxDynamicSharedMemorySize, XG_SMEM);
        cudaFuncSetAttribute(lstm_tc,   cudaFuncAttributeMaxDynamicSharedMemorySize, RC_SMEM);
        attr_set = true;
    }

    init_sync<<<1, 1>>>();
    split_x16<<<4096, 256>>>(x, kT * kB * kH);
    split_wih<<<1024, 256>>>(wih, kG * kH);
    split_h0_16<<<64, 256>>>(h0, kB * kH);
    pack_whh16<<<1024, 256>>>(whh);
    xgates_tc<<<dim3(kG / 128, (kT * kB) / 128), 256, XG_SMEM>>>(bih, bhh);
    lstm_tc<<<RBLK, 512, RC_SMEM>>>(c0, out);
}

// round 14
// speedup vs baseline: 1.3759x; 1.0142x over previous
#include <cuda_runtime.h>
#include <cuda_fp16.h>
#include <math.h>
#include <stdint.h>

typedef uint32_t u32;

static constexpr int kT = 512;
static constexpr int kB = 64;
static constexpr int kH = 1024;
static constexpr int kG = 4096;
static constexpr int RBLK = 128;

// ---------------- global scratch ----------------
__device__ __half g_xg16[(size_t)kT * kB * kG];    // x-gates fp16 (biases included)
__device__ __half g_x16[(size_t)kT * kB * kH];     // x fp16
__device__ __half g_wih[(size_t)kG * kH];          // W_ih fp16
__device__ __half g_wp[(size_t)kG * kH];           // W_hh fp16 packed [jblk][row][k]
__device__ __half g_h16[2][kB * kH];               // h fp16, double buffered [b][k]
__device__ unsigned g_cnt, g_rel;

// ---------------- PTX helpers ----------------
__device__ __forceinline__ u32 smem_u32(const void* p) {
    u32 a;
    asm("{ .reg .u64 t; cvta.to.shared.u64 t, %1; cvt.u32.u64 %0, t; }" : "=r"(a) : "l"(p));
    return a;
}
__device__ __forceinline__ void cp16(u32 dst, const void* src) {
    asm volatile("cp.async.cg.shared.global [%0], [%1], 16;" :: "r"(dst), "l"(src) : "memory");
}
__device__ __forceinline__ void cp_commit() { asm volatile("cp.async.commit_group;" ::: "memory"); }
__device__ __forceinline__ void cp_wait0()  { asm volatile("cp.async.wait_group 0;" ::: "memory"); }
__device__ __forceinline__ void cp_wait1()  { asm volatile("cp.async.wait_group 1;" ::: "memory"); }
__device__ __forceinline__ void cp_wait2()  { asm volatile("cp.async.wait_group 2;" ::: "memory"); }

__device__ __forceinline__ void ldm4(u32 a, u32* r) {
    asm volatile("ldmatrix.sync.aligned.m8n8.x4.shared.b16 {%0,%1,%2,%3}, [%4];"
                 : "=r"(r[0]), "=r"(r[1]), "=r"(r[2]), "=r"(r[3]) : "r"(a));
}
__device__ __forceinline__ void mma_fp16(float* c, const u32* a, u32 b0, u32 b1) {
    asm volatile("mma.sync.aligned.m16n8k16.row.col.f32.f16.f16.f32 "
                 "{%0,%1,%2,%3}, {%4,%5,%6,%7}, {%8,%9}, {%0,%1,%2,%3};"
                 : "+f"(c[0]), "+f"(c[1]), "+f"(c[2]), "+f"(c[3])
                 : "r"(a[0]), "r"(a[1]), "r"(a[2]), "r"(a[3]), "r"(b0), "r"(b1));
}
// swizzled byte offset: row r, 16B-unit u, row stride bytes (multiple of 128)
__device__ __forceinline__ u32 swof(int r, int u, int stride) {
    return (u32)(r * stride + ((u >> 3) << 7) + (((u ^ r) & 7) << 4));
}

__device__ __forceinline__ float sigf(float x) { return 1.f / (1.f + __expf(-x)); }
__device__ __forceinline__ float tanh_fast(float x) {
    float t = 2.f / (__expf(2.f * fabsf(x)) + 1.f);
    float r = 1.f - t;
    return x >= 0.f ? r : -r;
}

// ---------------- prep kernels ----------------
__global__ void split_x16(const float* __restrict__ s, int n) {
    for (int i = blockIdx.x * blockDim.x + threadIdx.x; i < n; i += gridDim.x * blockDim.x)
        g_x16[i] = __float2half_rn(s[i]);
}
// fused: W_ih convert, W_hh pack, h0 convert, sync-counter init
__global__ void prep_fused(const float* __restrict__ wih, const float* __restrict__ whh,
                           const float* __restrict__ h0) {
    const int n = kG * kH;
    for (int i = blockIdx.x * blockDim.x + threadIdx.x; i < n; i += gridDim.x * blockDim.x) {
        g_wih[i] = __float2half_rn(wih[i]);
        // g_wp[(jblk*32 + row)*1024 + k], row = g*8 + jl, src row = g*1024 + jblk*8 + jl
        int k    = i & 1023;
        int row  = (i >> 10) & 31;
        int jblk = i >> 15;
        int g = row >> 3, jl = row & 7;
        g_wp[i] = __float2half_rn(whh[(size_t)(g * kH + jblk * 8 + jl) * kH + k]);
        if (i < kB * kH) g_h16[0][i] = __float2half_rn(h0[i]);
        if (i == 0) { g_cnt = 0u; g_rel = 0u; }
    }
}

// ============================================================================
// Phase 1: x-gates GEMM (fp16 HMMA). C = x @ Wih^T + biases -> fp16 out.
// 128x128 tile, 256 thr, warp tile 32x64. K chunks of 64, TRIPLE buffered.
// ============================================================================
static constexpr int XA   = 0;
static constexpr int XWH  = 16384;
static constexpr int XBUFSZ = 32768;
static constexpr int XBIAS  = 3 * XBUFSZ;       // 98304
static constexpr int XG_SMEM = XBIAS + 512;     // 98816

__global__ __launch_bounds__(256, 2) void xgates_tc(
    const float* __restrict__ bih, const float* __restrict__ bhh)
{
    extern __shared__ char sm[];
    const u32 sb  = smem_u32(sm);
    const int tid = threadIdx.x;
    const int wid = tid >> 5;
    const int ln  = tid & 31;
    const int mg  = wid & 3;
    const int ng  = wid >> 2;
    const int n0  = blockIdx.x * 128;
    const int m0  = blockIdx.y * 128;
    float* bias_s = (float*)(sm + XBIAS);

    if (tid < 128) bias_s[tid] = bih[n0 + tid] + bhh[n0 + tid];

    auto stage = [&](int ch) {
        const u32 buf = sb + (ch % 3) * XBUFSZ;
        #pragma unroll
        for (int rep = 0; rep < 4; rep++) {
            int idx = tid + rep * 256;
            int r = idx >> 3, u = idx & 7;
            u32 sw = swof(r, u, 128);
            cp16(buf + XA  + sw, (const char*)g_x16 + ((size_t)(m0 + r) * kH + ch * 64 + u * 8) * 2);
            cp16(buf + XWH + sw, (const char*)g_wih + ((size_t)(n0 + r) * kH + ch * 64 + u * 8) * 2);
        }
        cp_commit();
    };

    float c[2][8][4];
    #pragma unroll
    for (int i = 0; i < 2; i++)
        #pragma unroll
        for (int j = 0; j < 8; j++)
            #pragma unroll
            for (int q = 0; q < 4; q++) c[i][j][q] = 0.f;

    stage(0);
    stage(1);
    for (int ch = 0; ch < 16; ch++) {
        if (ch + 2 < 16) stage(ch + 2);      // buf (ch+2)%3: last read compute(ch-1), protected by trailing sync
        if (ch < 14) cp_wait2();
        else if (ch == 14) cp_wait1();
        else cp_wait0();
        __syncthreads();
        const u32 buf = sb + (ch % 3) * XBUFSZ;
        #pragma unroll
        for (int k2 = 0; k2 < 4; k2++) {
            u32 ah[2][4];
            #pragma unroll
            for (int mt = 0; mt < 2; mt++) {
                int r = mg * 32 + mt * 16 + (ln & 15);
                int u = k2 * 2 + (ln >> 4);
                ldm4(buf + XA + swof(r, u, 128), ah[mt]);
            }
            u32 bh[4][4];
            #pragma unroll
            for (int p = 0; p < 4; p++) {
                int r = ng * 64 + p * 16 + (ln & 7) + ((ln & 16) >> 1);
                int u = k2 * 2 + ((ln >> 3) & 1);
                ldm4(buf + XWH + swof(r, u, 128), bh[p]);
            }
            #pragma unroll
            for (int mt = 0; mt < 2; mt++)
                #pragma unroll
                for (int nt = 0; nt < 8; nt++) {
                    const int p = nt >> 1, o = (nt & 1) * 2;
                    mma_fp16(c[mt][nt], ah[mt], bh[p][o], bh[p][o + 1]);
                }
        }
        __syncthreads();
    }

    // epilogue: add bias, store fp16 pairs
    #pragma unroll
    for (int mt = 0; mt < 2; mt++) {
        const int row = m0 + mg * 32 + mt * 16 + (ln >> 2);
        #pragma unroll
        for (int nt = 0; nt < 8; nt++) {
            const int col = ng * 64 + nt * 8 + (ln & 3) * 2;
            float b0 = bias_s[col], b1 = bias_s[col + 1];
            __half2 v0 = __floats2half2_rn(c[mt][nt][0] + b0, c[mt][nt][1] + b1);
            __half2 v1 = __floats2half2_rn(c[mt][nt][2] + b0, c[mt][nt][3] + b1);
            *(__half2*)(g_xg16 + (size_t)row * kG + n0 + col)       = v0;
            *(__half2*)(g_xg16 + (size_t)(row + 8) * kG + n0 + col) = v1;
        }
    }
}

// ============================================================================
// Phase 2: persistent recurrence (R13 structure, 3-buffer chunk pipeline).
// 128 blocks x 512 threads. Block jblk: C[32 gate-rows, 64 batch] = Wslice @ h^T.
// W fp16 resident (64 KB). h: 4 chunks of K=256 (32 KB), 3 buffers.
// 16 warps: mg(2) x ng(4) x ks(2). Warp tile 16x16, 2 accumulators. c in regs.
// Single-counter barrier.
// ============================================================================
static constexpr int RWH   = 0;                 // 64 KB resident W
static constexpr int RBUF  = 65536;             // 3 x 32 KB h chunk buffers
static constexpr int RRED  = RBUF + 98304;      // 163840 : 2*32*68 fp32 = 17408
static constexpr int RC_SMEM = RRED + 17408;    // 181248

__global__ __launch_bounds__(512, 1) void lstm_tc(
    const float* __restrict__ c0, float* __restrict__ out)
{
    extern __shared__ char sm[];
    const u32 sb  = smem_u32(sm);
    const int tid = threadIdx.x;
    const int wid = tid >> 5;
    const int ln  = tid & 31;
    const int jblk = blockIdx.x;
    const int j0   = jblk * 8;
    const int mg = wid & 1, ng = (wid >> 1) & 3, ks = wid >> 3;
    float* red = (float*)(sm + RRED);

    // resident W load: 32 rows x 128 units, swizzled, stride 2048 B
    #pragma unroll
    for (int rep = 0; rep < 8; rep++) {
        int idx = tid + rep * 512;
        int r = idx >> 7, u = idx & 127;
        cp16(sb + RWH + swof(r, u, 2048),
             (const char*)g_wp + ((size_t)(jblk * 32 + r) * kH + u * 8) * 2);
    }
    cp_commit();

    // cell ownership: b = tid>>3, jl = tid&7 ; c-state in a register
    const int cb  = tid >> 3;
    const int cjl = tid & 7;
    float creg = c0[(size_t)cb * kH + j0 + cjl];

    cp_wait0();
    __syncthreads();

    for (int t = 0; t < kT; t++) {
        const __half* hsrc = g_h16[t & 1];

        // x-gates prefetch (fp16, biases included)
        float xgv[4];
        {
            const __half* xp = g_xg16 + ((size_t)t * kB + cb) * kG + j0 + cjl;
            #pragma unroll
            for (int g = 0; g < 4; g++) xgv[g] = __half2float(xp[g * kH]);
        }

        // stage chunk ch (64 rows x 32 units, K=256) into buffer buf
        auto stage = [&](int ch, u32 buf) {
            #pragma unroll
            for (int rep = 0; rep < 4; rep++) {
                int idx = tid + rep * 512;   // 0..2047
                int r = idx >> 5, u = idx & 31;
                cp16(buf + swof(r, u, 512),
                     (const char*)hsrc + ((size_t)r * kH + ch * 256 + u * 8) * 2);
            }
            cp_commit();
        };

        float cc[2][4];
        #pragma unroll
        for (int i = 0; i < 2; i++)
            #pragma unroll
            for (int q = 0; q < 4; q++) cc[i][q] = 0.f;

        // MMA over one staged chunk ci (K=256 -> 16 k16, split over ks(2))
        auto mma_chunk = [&](int ci, u32 buf) {
            #pragma unroll
            for (int k2 = 0; k2 < 8; k2++) {
                const int lk = ks * 8 + k2;          // local k16 in chunk 0..15
                const int gk = ci * 16 + lk;         // global k16 0..63
                u32 aa[4], bb[4];
                {
                    int r = mg * 16 + (ln & 15);
                    int u = gk * 2 + (ln >> 4);
                    ldm4(sb + RWH + swof(r, u, 2048), aa);
                }
                {
                    int r = ng * 16 + (ln & 7) + ((ln & 16) >> 1);
                    int u = lk * 2 + ((ln >> 3) & 1);
                    ldm4(buf + swof(r, u, 512), bb);
                }
                mma_fp16(cc[0], aa, bb[0], bb[1]);
                mma_fp16(cc[1], aa, bb[2], bb[3]);
            }
        };

        const u32 b0 = sb + RBUF, b1 = sb + RBUF + 32768, b2 = sb + RBUF + 65536;
        stage(0, b0);
        stage(1, b1);
        stage(2, b2);
        cp_wait2(); __syncthreads();     // chunk0 resident
        mma_chunk(0, b0);
        __syncthreads();                 // all reads of b0 done
        stage(3, b0);
        cp_wait2(); __syncthreads();     // chunk1 resident
        mma_chunk(1, b1);
        cp_wait1(); __syncthreads();     // chunk2 resident
        mma_chunk(2, b2);
        cp_wait0(); __syncthreads();     // chunk3 resident
        mma_chunk(3, b0);

        // C frags -> red[ks][row][col]
        {
            float* rp = red + ks * (32 * 68);
            const int r0  = mg * 16 + (ln >> 2);
            const int col = ng * 16 + (ln & 3) * 2;
            *(float2*)(rp + r0 * 68 + col)           = make_float2(cc[0][0], cc[0][1]);
            *(float2*)(rp + (r0 + 8) * 68 + col)     = make_float2(cc[0][2], cc[0][3]);
            *(float2*)(rp + r0 * 68 + col + 8)       = make_float2(cc[1][0], cc[1][1]);
            *(float2*)(rp + (r0 + 8) * 68 + col + 8) = make_float2(cc[1][2], cc[1][3]);
        }
        __syncthreads();

        // fused cell update (c-state in register)
        {
            float gv[4];
            #pragma unroll
            for (int g = 0; g < 4; g++) {
                const int row = g * 8 + cjl;
                gv[g] = red[row * 68 + cb] + red[32 * 68 + row * 68 + cb] + xgv[g];
            }
            float gi = sigf(gv[0]);
            float gf = sigf(gv[1]);
            float gg = tanh_fast(gv[2]);
            float go = sigf(gv[3]);
            creg = gf * creg + gi * gg;
            float hy = go * tanh_fast(creg);
            out[((size_t)t * kB + cb) * kH + j0 + cjl] = hy;
            g_h16[(t & 1) ^ 1][(size_t)cb * kH + j0 + cjl] = __float2half_rn(hy);
        }

        // single-counter grid barrier between steps
        if (t < kT - 1) {
            __threadfence();
            __syncthreads();
            if (tid == 0) {
                unsigned a = atomicAdd(&g_cnt, 1u) + 1u;
                if (a == (unsigned)(t + 1) * RBLK) {
                    __threadfence();
                    atomicExch(&g_rel, (unsigned)(t + 1));
                } else {
                    while (*((volatile unsigned*)&g_rel) < (unsigned)(t + 1)) { }
                }
            }
            __syncthreads();
        }
    }

    // final cell state
    out[(size_t)kT * kB * kH + (size_t)cb * kH + j0 + cjl] = creg;
}

// ============================================================================
extern "C" void kernel_launch(void* const* d_in, const int* in_sizes, int n_in,
                              void* d_out, int out_size) {
    const float* x   = (const float*)d_in[0];
    const float* h0  = (const float*)d_in[1];
    const float* c0  = (const float*)d_in[2];
    const float* wih = (const float*)d_in[3];
    const float* whh = (const float*)d_in[4];
    const float* bih = (const float*)d_in[5];
    const float* bhh = (const float*)d_in[6];
    float* out = (float*)d_out;

    static bool attr_set = false;
    if (!attr_set) {
        cudaFuncSetAttribute(xgates_tc, cudaFuncAttributeMaxDynamicSharedMemorySize, XG_SMEM);
        cudaFuncSetAttribute(lstm_tc,   cudaFuncAttributeMaxDynamicSharedMemorySize, RC_SMEM);
        attr_set = true;
    }

    split_x16<<<4096, 256>>>(x, kT * kB * kH);
    prep_fused<<<1024, 256>>>(wih, whh, h0);
    xgates_tc<<<dim3(kG / 128, (kT * kB) / 128), 256, XG_SMEM>>>(bih, bhh);
    lstm_tc<<<RBLK, 512, RC_SMEM>>>(c0, out);
}

// round 16
// speedup vs baseline: 1.4123x; 1.0264x over previous
#include <cuda_runtime.h>
#include <cuda_fp16.h>
#include <math.h>
#include <stdint.h>

typedef uint32_t u32;

static constexpr int kT = 512;
static constexpr int kB = 64;
static constexpr int kH = 1024;
static constexpr int kG = 4096;
static constexpr int RBLK = 128;

// ---------------- global scratch ----------------
__device__ __half g_xg16[(size_t)kT * kB * kG];    // x-gates fp16 (biases included)
__device__ __half g_x16[(size_t)kT * kB * kH];     // x fp16
__device__ __half g_wih[(size_t)kG * kH];          // W_ih fp16
__device__ __half g_wp[(size_t)kG * kH];           // W_hh fp16 packed [jblk][row][k]
__device__ __half g_h16[2][kB * kH];               // h fp16, double buffered [b][k]
__device__ unsigned g_cnt, g_rel;

// ---------------- PTX helpers ----------------
__device__ __forceinline__ u32 smem_u32(const void* p) {
    u32 a;
    asm("{ .reg .u64 t; cvta.to.shared.u64 t, %1; cvt.u32.u64 %0, t; }" : "=r"(a) : "l"(p));
    return a;
}
__device__ __forceinline__ void cp16(u32 dst, const void* src) {
    asm volatile("cp.async.cg.shared.global [%0], [%1], 16;" :: "r"(dst), "l"(src) : "memory");
}
__device__ __forceinline__ void cp_commit() { asm volatile("cp.async.commit_group;" ::: "memory"); }
__device__ __forceinline__ void cp_wait0()  { asm volatile("cp.async.wait_group 0;" ::: "memory"); }
__device__ __forceinline__ void cp_wait1()  { asm volatile("cp.async.wait_group 1;" ::: "memory"); }
__device__ __forceinline__ void cp_wait2()  { asm volatile("cp.async.wait_group 2;" ::: "memory"); }
__device__ __forceinline__ void cp_wait3()  { asm volatile("cp.async.wait_group 3;" ::: "memory"); }

__device__ __forceinline__ void ldm4(u32 a, u32* r) {
    asm volatile("ldmatrix.sync.aligned.m8n8.x4.shared.b16 {%0,%1,%2,%3}, [%4];"
                 : "=r"(r[0]), "=r"(r[1]), "=r"(r[2]), "=r"(r[3]) : "r"(a));
}
__device__ __forceinline__ void mma_fp16(float* c, const u32* a, u32 b0, u32 b1) {
    asm volatile("mma.sync.aligned.m16n8k16.row.col.f32.f16.f16.f32 "
                 "{%0,%1,%2,%3}, {%4,%5,%6,%7}, {%8,%9}, {%0,%1,%2,%3};"
                 : "+f"(c[0]), "+f"(c[1]), "+f"(c[2]), "+f"(c[3])
                 : "r"(a[0]), "r"(a[1]), "r"(a[2]), "r"(a[3]), "r"(b0), "r"(b1));
}
// swizzled byte offset: row r, 16B-unit u, row stride bytes (multiple of 128)
__device__ __forceinline__ u32 swof(int r, int u, int stride) {
    return (u32)(r * stride + ((u >> 3) << 7) + (((u ^ r) & 7) << 4));
}

__device__ __forceinline__ float sigf(float x) { return 1.f / (1.f + __expf(-x)); }
__device__ __forceinline__ float tanh_fast(float x) {
    float t = 2.f / (__expf(2.f * fabsf(x)) + 1.f);
    float r = 1.f - t;
    return x >= 0.f ? r : -r;
}

// ---------------- prep kernels ----------------
__global__ void split_x16(const float* __restrict__ s, int n) {
    for (int i = blockIdx.x * blockDim.x + threadIdx.x; i < n; i += gridDim.x * blockDim.x)
        g_x16[i] = __float2half_rn(s[i]);
}
// fused: W_ih convert, W_hh pack, h0 convert, sync-counter init
__global__ void prep_fused(const float* __restrict__ wih, const float* __restrict__ whh,
                           const float* __restrict__ h0) {
    const int n = kG * kH;
    for (int i = blockIdx.x * blockDim.x + threadIdx.x; i < n; i += gridDim.x * blockDim.x) {
        g_wih[i] = __float2half_rn(wih[i]);
        int k    = i & 1023;
        int row  = (i >> 10) & 31;
        int jblk = i >> 15;
        int g = row >> 3, jl = row & 7;
        g_wp[i] = __float2half_rn(whh[(size_t)(g * kH + jblk * 8 + jl) * kH + k]);
        if (i < kB * kH) g_h16[0][i] = __float2half_rn(h0[i]);
        if (i == 0) { g_cnt = 0u; g_rel = 0u; }
    }
}

// ============================================================================
// Phase 1: x-gates GEMM (fp16 HMMA). C = x @ Wih^T + biases -> fp16 out.
// 128x128 tile, 256 thr, warp tile 32x64. K chunks of 64, TRIPLE buffered.
// ============================================================================
static constexpr int XA   = 0;
static constexpr int XWH  = 16384;
static constexpr int XBUFSZ = 32768;
static constexpr int XBIAS  = 3 * XBUFSZ;       // 98304
static constexpr int XG_SMEM = XBIAS + 512;     // 98816

__global__ __launch_bounds__(256, 2) void xgates_tc(
    const float* __restrict__ bih, const float* __restrict__ bhh)
{
    extern __shared__ char sm[];
    const u32 sb  = smem_u32(sm);
    const int tid = threadIdx.x;
    const int wid = tid >> 5;
    const int ln  = tid & 31;
    const int mg  = wid & 3;
    const int ng  = wid >> 2;
    const int n0  = blockIdx.x * 128;
    const int m0  = blockIdx.y * 128;
    float* bias_s = (float*)(sm + XBIAS);

    if (tid < 128) bias_s[tid] = bih[n0 + tid] + bhh[n0 + tid];

    auto stage = [&](int ch) {
        const u32 buf = sb + (ch % 3) * XBUFSZ;
        #pragma unroll
        for (int rep = 0; rep < 4; rep++) {
            int idx = tid + rep * 256;
            int r = idx >> 3, u = idx & 7;
            u32 sw = swof(r, u, 128);
            cp16(buf + XA  + sw, (const char*)g_x16 + ((size_t)(m0 + r) * kH + ch * 64 + u * 8) * 2);
            cp16(buf + XWH + sw, (const char*)g_wih + ((size_t)(n0 + r) * kH + ch * 64 + u * 8) * 2);
        }
        cp_commit();
    };

    float c[2][8][4];
    #pragma unroll
    for (int i = 0; i < 2; i++)
        #pragma unroll
        for (int j = 0; j < 8; j++)
            #pragma unroll
            for (int q = 0; q < 4; q++) c[i][j][q] = 0.f;

    stage(0);
    stage(1);
    for (int ch = 0; ch < 16; ch++) {
        if (ch + 2 < 16) stage(ch + 2);
        if (ch < 14) cp_wait2();
        else if (ch == 14) cp_wait1();
        else cp_wait0();
        __syncthreads();
        const u32 buf = sb + (ch % 3) * XBUFSZ;
        #pragma unroll
        for (int k2 = 0; k2 < 4; k2++) {
            u32 ah[2][4];
            #pragma unroll
            for (int mt = 0; mt < 2; mt++) {
                int r = mg * 32 + mt * 16 + (ln & 15);
                int u = k2 * 2 + (ln >> 4);
                ldm4(buf + XA + swof(r, u, 128), ah[mt]);
            }
            u32 bh[4][4];
            #pragma unroll
            for (int p = 0; p < 4; p++) {
                int r = ng * 64 + p * 16 + (ln & 7) + ((ln & 16) >> 1);
                int u = k2 * 2 + ((ln >> 3) & 1);
                ldm4(buf + XWH + swof(r, u, 128), bh[p]);
            }
            #pragma unroll
            for (int mt = 0; mt < 2; mt++)
                #pragma unroll
                for (int nt = 0; nt < 8; nt++) {
                    const int p = nt >> 1, o = (nt & 1) * 2;
                    mma_fp16(c[mt][nt], ah[mt], bh[p][o], bh[p][o + 1]);
                }
        }
        __syncthreads();
    }

    // epilogue: add bias, store fp16 pairs
    #pragma unroll
    for (int mt = 0; mt < 2; mt++) {
        const int row = m0 + mg * 32 + mt * 16 + (ln >> 2);
        #pragma unroll
        for (int nt = 0; nt < 8; nt++) {
            const int col = ng * 64 + nt * 8 + (ln & 3) * 2;
            float b0 = bias_s[col], b1 = bias_s[col + 1];
            __half2 v0 = __floats2half2_rn(c[mt][nt][0] + b0, c[mt][nt][1] + b1);
            __half2 v1 = __floats2half2_rn(c[mt][nt][2] + b0, c[mt][nt][3] + b1);
            *(__half2*)(g_xg16 + (size_t)row * kG + n0 + col)       = v0;
            *(__half2*)(g_xg16 + (size_t)(row + 8) * kG + n0 + col) = v1;
        }
    }
}

// ============================================================================
// Phase 2: persistent recurrence (4-buffer, stage-all-up-front pipeline).
// 128 blocks x 512 threads. Block jblk: C[32 gate-rows, 64 batch] = Wslice @ h^T.
// W fp16 resident (64 KB). h: 4 chunks of K=256 (32 KB), 4 buffers, all staged
// at step start; wait3/2/1/0 ladder. 16 warps: mg(2) x ng(4) x ks(2). c in regs.
// Fence-free barrier: atom.acq_rel arrival + st.release publish + ld.acquire spin.
// ============================================================================
static constexpr int RWH   = 0;                 // 64 KB resident W
static constexpr int RBUF  = 65536;             // 4 x 32 KB h chunk buffers
static constexpr int RRED  = RBUF + 131072;     // 196608 : 2*32*68 fp32 = 17408
static constexpr int RC_SMEM = RRED + 17408;    // 214016

__global__ __launch_bounds__(512, 1) void lstm_tc(
    const float* __restrict__ c0, float* __restrict__ out)
{
    extern __shared__ char sm[];
    const u32 sb  = smem_u32(sm);
    const int tid = threadIdx.x;
    const int wid = tid >> 5;
    const int ln  = tid & 31;
    const int jblk = blockIdx.x;
    const int j0   = jblk * 8;
    const int mg = wid & 1, ng = (wid >> 1) & 3, ks = wid >> 3;
    float* red = (float*)(sm + RRED);

    // resident W load: 32 rows x 128 units, swizzled, stride 2048 B
    #pragma unroll
    for (int rep = 0; rep < 8; rep++) {
        int idx = tid + rep * 512;
        int r = idx >> 7, u = idx & 127;
        cp16(sb + RWH + swof(r, u, 2048),
             (const char*)g_wp + ((size_t)(jblk * 32 + r) * kH + u * 8) * 2);
    }
    cp_commit();

    // cell ownership: b = tid>>3, jl = tid&7 ; c-state in a register
    const int cb  = tid >> 3;
    const int cjl = tid & 7;
    float creg = c0[(size_t)cb * kH + j0 + cjl];

    cp_wait0();
    __syncthreads();

    for (int t = 0; t < kT; t++) {
        const __half* hsrc = g_h16[t & 1];

        // x-gates prefetch (fp16, biases included)
        float xgv[4];
        {
            const __half* xp = g_xg16 + ((size_t)t * kB + cb) * kG + j0 + cjl;
            #pragma unroll
            for (int g = 0; g < 4; g++) xgv[g] = __half2float(xp[g * kH]);
        }

        // stage chunk ch (64 rows x 32 units, K=256) into buffer buf
        auto stage = [&](int ch, u32 buf) {
            #pragma unroll
            for (int rep = 0; rep < 4; rep++) {
                int idx = tid + rep * 512;   // 0..2047
                int r = idx >> 5, u = idx & 31;
                cp16(buf + swof(r, u, 512),
                     (const char*)hsrc + ((size_t)r * kH + ch * 256 + u * 8) * 2);
            }
            cp_commit();
        };

        float cc[2][4];
        #pragma unroll
        for (int i = 0; i < 2; i++)
            #pragma unroll
            for (int q = 0; q < 4; q++) cc[i][q] = 0.f;

        // MMA over one staged chunk ci (K=256 -> 16 k16, split over ks(2))
        auto mma_chunk = [&](int ci, u32 buf) {
            #pragma unroll
            for (int k2 = 0; k2 < 8; k2++) {
                const int lk = ks * 8 + k2;          // local k16 in chunk 0..15
                const int gk = ci * 16 + lk;         // global k16 0..63
                u32 aa[4], bb[4];
                {
                    int r = mg * 16 + (ln & 15);
                    int u = gk * 2 + (ln >> 4);
                    ldm4(sb + RWH + swof(r, u, 2048), aa);
                }
                {
                    int r = ng * 16 + (ln & 7) + ((ln & 16) >> 1);
                    int u = lk * 2 + ((ln >> 3) & 1);
                    ldm4(buf + swof(r, u, 512), bb);
                }
                mma_fp16(cc[0], aa, bb[0], bb[1]);
                mma_fp16(cc[1], aa, bb[2], bb[3]);
            }
        };

        const u32 hb0 = sb + RBUF, hb1 = hb0 + 32768, hb2 = hb1 + 32768, hb3 = hb2 + 32768;
        stage(0, hb0);
        stage(1, hb1);
        stage(2, hb2);
        stage(3, hb3);
        cp_wait3(); __syncthreads();
        mma_chunk(0, hb0);
        cp_wait2(); __syncthreads();
        mma_chunk(1, hb1);
        cp_wait1(); __syncthreads();
        mma_chunk(2, hb2);
        cp_wait0(); __syncthreads();
        mma_chunk(3, hb3);

        // C frags -> red[ks][row][col]
        {
            float* rp = red + ks * (32 * 68);
            const int r0  = mg * 16 + (ln >> 2);
            const int col = ng * 16 + (ln & 3) * 2;
            *(float2*)(rp + r0 * 68 + col)           = make_float2(cc[0][0], cc[0][1]);
            *(float2*)(rp + (r0 + 8) * 68 + col)     = make_float2(cc[0][2], cc[0][3]);
            *(float2*)(rp + r0 * 68 + col + 8)       = make_float2(cc[1][0], cc[1][1]);
            *(float2*)(rp + (r0 + 8) * 68 + col + 8) = make_float2(cc[1][2], cc[1][3]);
        }
        __syncthreads();

        // fused cell update (c-state in register)
        {
            float gv[4];
            #pragma unroll
            for (int g = 0; g < 4; g++) {
                const int row = g * 8 + cjl;
                gv[g] = red[row * 68 + cb] + red[32 * 68 + row * 68 + cb] + xgv[g];
            }
            float gi = sigf(gv[0]);
            float gf = sigf(gv[1]);
            float gg = tanh_fast(gv[2]);
            float go = sigf(gv[3]);
            creg = gf * creg + gi * gg;
            float hy = go * tanh_fast(creg);
            out[((size_t)t * kB + cb) * kH + j0 + cjl] = hy;
            g_h16[(t & 1) ^ 1][(size_t)cb * kH + j0 + cjl] = __float2half_rn(hy);
        }

        // fence-free grid barrier: acq_rel arrival, release publish, acquire spin
        if (t < kT - 1) {
            __syncthreads();   // all h-stores in-flight before the releasing atomic
            if (tid == 0) {
                const unsigned tgt = (unsigned)(t + 1);
                unsigned a;
                asm volatile("atom.acq_rel.gpu.global.add.u32 %0, [%1], 1;"
                             : "=r"(a) : "l"(&g_cnt) : "memory");
                if (a + 1u == tgt * (unsigned)RBLK) {
                    asm volatile("st.release.gpu.global.u32 [%0], %1;"
                                 :: "l"(&g_rel), "r"(tgt) : "memory");
                } else {
                    unsigned v;
                    do {
                        asm volatile("ld.acquire.gpu.global.u32 %0, [%1];"
                                     : "=r"(v) : "l"(&g_rel) : "memory");
                    } while (v < tgt);
                }
            }
            __syncthreads();
        }
    }

    // final cell state
    out[(size_t)kT * kB * kH + (size_t)cb * kH + j0 + cjl] = creg;
}

// ============================================================================
extern "C" void kernel_launch(void* const* d_in, const int* in_sizes, int n_in,
                              void* d_out, int out_size) {
    const float* x   = (const float*)d_in[0];
    const float* h0  = (const float*)d_in[1];
    const float* c0  = (const float*)d_in[2];
    const float* wih = (const float*)d_in[3];
    const float* whh = (const float*)d_in[4];
    const float* bih = (const float*)d_in[5];
    const float* bhh = (const float*)d_in[6];
    float* out = (float*)d_out;

    static bool attr_set = false;
    if (!attr_set) {
        cudaFuncSetAttribute(xgates_tc, cudaFuncAttributeMaxDynamicSharedMemorySize, XG_SMEM);
        cudaFuncSetAttribute(lstm_tc,   cudaFuncAttributeMaxDynamicSharedMemorySize, RC_SMEM);
        attr_set = true;
    }

    split_x16<<<4096, 256>>>(x, kT * kB * kH);
    prep_fused<<<1024, 256>>>(wih, whh, h0);
    xgates_tc<<<dim3(kG / 128, (kT * kB) / 128), 256, XG_SMEM>>>(bih, bhh);
    lstm_tc<<<RBLK, 512, RC_SMEM>>>(c0, out);
}